// round 2
// baseline (speedup 1.0000x reference)
#include <cuda_runtime.h>
#include <cuda_bf16.h>
#include <stdint.h>

#define NB 32
#define NT 96
#define NH 512
#define NV 10000
#define NU 2560   // U layout: [x_a:0, ha:512, x_f:1024, hf:1536, att:2048]

__device__ __nv_bfloat16 g_embed[NV * NH];
__device__ __nv_bfloat16 g_Wcat[NU * NU];   // rows: [in(512)|out(512)|cell(512)|f1(512)|f2(512)], cols: U order
__device__ __nv_bfloat16 g_logW[NV * NH];
__device__ __nv_bfloat16 g_U[NB * NU];
__device__ float         g_part[4 * NB * NU];
__device__ __nv_bfloat16 g_h[NB * NT * NH];
__device__ float         g_c[NB * NT * NH];

__device__ __forceinline__ uint32_t smem_u32(const void* p) {
    return (uint32_t)__cvta_generic_to_shared(p);
}
__device__ __forceinline__ void ldm_x4(uint32_t* r, uint32_t a) {
    asm volatile("ldmatrix.sync.aligned.m8n8.x4.shared.b16 {%0,%1,%2,%3}, [%4];"
                 : "=r"(r[0]), "=r"(r[1]), "=r"(r[2]), "=r"(r[3]) : "r"(a));
}
__device__ __forceinline__ void mma16816(float* d, const uint32_t* a, const uint32_t* b) {
    asm volatile("mma.sync.aligned.m16n8k16.row.col.f32.bf16.bf16.f32 "
                 "{%0,%1,%2,%3}, {%4,%5,%6,%7}, {%8,%9}, {%0,%1,%2,%3};"
                 : "+f"(d[0]), "+f"(d[1]), "+f"(d[2]), "+f"(d[3])
                 : "r"(a[0]), "r"(a[1]), "r"(a[2]), "r"(a[3]), "r"(b[0]), "r"(b[1]));
}
__device__ __forceinline__ float sigm(float x) { return 1.f / (1.f + __expf(-x)); }

// ---------- init: bf16 conversions + Wcat assembly + zero dynamic U ----------
__global__ void init_convert(const float* __restrict__ embed, const float* __restrict__ WH,
                             const float* __restrict__ WI, const float* __restrict__ Wf1,
                             const float* __restrict__ Wf2, const float* __restrict__ logW) {
    int st = gridDim.x * blockDim.x, t0 = blockIdx.x * blockDim.x + threadIdx.x;
    for (int i = t0; i < NV * NH; i += st) g_embed[i] = __float2bfloat16(embed[i]);
    for (int i = t0; i < NV * NH; i += st) g_logW[i]  = __float2bfloat16(logW[i]);
    for (int i = t0; i < NU * NU; i += st) {
        int n = i / NU, u = i - n * NU;
        // map U index -> native col index of [x_a, x_f, ha, hf(, att)]
        int m = (u < 512) ? u : (u < 1024 ? u + 512 : (u < 1536 ? u - 512 : u));
        float v = 0.f;
        if (n < 1024)      { if (u < 2048) v = WH[n * 2048 + m]; }
        else if (n < 1536) { v = WI[(n - 1024) * 2560 + m]; }
        else if (n < 2048) { if (u < 1024) v = Wf1[(n - 1536) * 1024 + u]; }
        else               { if (u >= 1024 && u < 2048)
                               v = Wf2[(n - 2048) * 1024 + (u < 1536 ? u - 1024 : u - 512)]; }
        g_Wcat[i] = __float2bfloat16(v);
    }
    for (int i = t0; i < NB * 2048; i += st)
        g_U[(i >> 11) * NU + (i & 2047)] = __float2bfloat16(0.f);
}

// ---------- att = fc_feats @ fc_W^T + fc_b -> U[:,2048:2560] ----------
__global__ __launch_bounds__(256) void att_kernel(const float* __restrict__ x,
                                                  const float* __restrict__ W,
                                                  const float* __restrict__ bias) {
    int gw = (blockIdx.x * 256 + threadIdx.x) >> 5, lane = threadIdx.x & 31;
    int b = gw >> 9, j = gw & 511;
    const float4* xa = (const float4*)(x + b * 2048);
    const float4* wa = (const float4*)(W + j * 2048);
    float s = 0.f;
    for (int k = lane; k < 512; k += 32) {
        float4 u = xa[k], v = wa[k];
        s += u.x * v.x + u.y * v.y + u.z * v.z + u.w * v.w;
    }
#pragma unroll
    for (int o = 16; o; o >>= 1) s += __shfl_xor_sync(~0u, s, o);
    if (!lane) g_U[b * NU + 2048 + j] = __float2bfloat16(s + bias[j]);
}

// ---------- step GEMM: part[kp] += U[32,K=640] @ Wcat[ntile,K]^T ----------
__global__ __launch_bounds__(256) void step_gemm() {
    __shared__ __align__(16) __nv_bfloat16 As[32][72];
    __shared__ __align__(16) __nv_bfloat16 Bs[64][72];
    int kp = blockIdx.x & 3, nblk = blockIdx.x >> 2;  // 160 blocks
    int K0 = kp * 640;
    int tid = threadIdx.x, lane = tid & 31, warp = tid >> 5;
    int arow = tid >> 3, acg = tid & 7;
    const uint4* ap  = (const uint4*)(g_U + arow * NU + K0 + acg * 8);
    const uint4* bp0 = (const uint4*)(g_Wcat + (nblk * 64 + arow) * NU + K0 + acg * 8);
    const uint4* bp1 = (const uint4*)(g_Wcat + (nblk * 64 + arow + 32) * NU + K0 + acg * 8);
    uint4 ra = ap[0], rb0 = bp0[0], rb1 = bp1[0];
    int wm = warp & 1, wn = warp >> 1;
    uint32_t ab = smem_u32(&As[wm * 16 + (lane & 15)][(lane >> 4) * 8]);
    uint32_t bb = smem_u32(&Bs[wn * 16 + (lane & 15)][(lane >> 4) * 8]);
    float acc0[4] = {0, 0, 0, 0}, acc1[4] = {0, 0, 0, 0};
#pragma unroll 1
    for (int kk = 0; kk < 10; kk++) {
        *(uint4*)&As[arow][acg * 8] = ra;
        *(uint4*)&Bs[arow][acg * 8] = rb0;
        *(uint4*)&Bs[arow + 32][acg * 8] = rb1;
        __syncthreads();
        if (kk < 9) { ra = ap[(kk + 1) * 8]; rb0 = bp0[(kk + 1) * 8]; rb1 = bp1[(kk + 1) * 8]; }
#pragma unroll
        for (int k16 = 0; k16 < 4; k16++) {
            uint32_t a[4], q[4];
            ldm_x4(a, ab + k16 * 32);
            ldm_x4(q, bb + k16 * 32);
            uint32_t b0[2] = {q[0], q[2]}, b1[2] = {q[1], q[3]};
            mma16816(acc0, a, b0);
            mma16816(acc1, a, b1);
        }
        __syncthreads();
    }
    int g = lane >> 2, tg = lane & 3;
    float* P = g_part + kp * (NB * NU);
    int n0 = nblk * 64 + wn * 16 + tg * 2, r0 = wm * 16 + g;
    *(float2*)&P[r0 * NU + n0]           = make_float2(acc0[0], acc0[1]);
    *(float2*)&P[(r0 + 8) * NU + n0]     = make_float2(acc0[2], acc0[3]);
    *(float2*)&P[r0 * NU + n0 + 8]       = make_float2(acc1[0], acc1[1]);
    *(float2*)&P[(r0 + 8) * NU + n0 + 8] = make_float2(acc1[2], acc1[3]);
}

// ---------- combine: activations + c/h update + gather U for t+1 ----------
__global__ __launch_bounds__(256) void step_combine(int t, const int* __restrict__ wi,
                                                    const int* __restrict__ fi,
                                                    const float* __restrict__ bH,
                                                    const float* __restrict__ bI,
                                                    const float* __restrict__ b1,
                                                    const float* __restrict__ b2) {
    int idx = blockIdx.x * 256 + threadIdx.x;  // 16384
    int b = idx >> 9, j = idx & 511;
    const float* P = g_part + b * NU;
    const int S = NB * NU;
#define SUM4(n) (P[n] + P[S + (n)] + P[2 * S + (n)] + P[3 * S + (n)])
    float ig = sigm(bH[j] + SUM4(j));
    float og = sigm(bH[512 + j] + SUM4(512 + j));
    float cg = tanhf(bI[j] + SUM4(1024 + j));
    float f1 = sigm(b1[j] + SUM4(1536 + j));
    float f2 = sigm(b2[j] + SUM4(2048 + j));
#undef SUM4
    float ca = 0.f, cf = 0.f;
    if (t > 0) ca = g_c[(b * NT + fi[b * NT + t]) * NH + j];
    if (!(t == 0 || ((t - 1) % 3) == 0)) cf = g_c[(b * NT + t - 1) * NH + j];
    float c = f1 * ca + f2 * cf + ig * cg;
    float h = og * tanhf(c);
    g_c[(b * NT + t) * NH + j] = c;
    __nv_bfloat16 hb = __float2bfloat16(h);
    g_h[(b * NT + t) * NH + j] = hb;
    int t1 = t + 1;
    if (t1 < NT) {
        int fa = fi[b * NT + t1];
        __nv_bfloat16 z = __float2bfloat16(0.f);
        __nv_bfloat16* U = g_U + b * NU;
        U[512 + j]  = (fa == t) ? hb : g_h[(b * NT + fa) * NH + j];   // ha
        U[j]        = g_embed[wi[b * NT + fa] * NH + j];              // x_a
        bool sib0 = ((t1 - 1) % 3) == 0;
        U[1536 + j] = sib0 ? z : hb;                                  // hf = h[t]
        U[1024 + j] = sib0 ? z : g_embed[wi[b * NT + t] * NH + j];    // x_f
    }
}

// ---------- logits: out[3072,10000] = h @ logW^T + b ----------
__global__ __launch_bounds__(256) void logits_gemm(const float* __restrict__ lb,
                                                   float* __restrict__ out) {
    __shared__ __align__(16) __nv_bfloat16 As[64][72];
    __shared__ __align__(16) __nv_bfloat16 Bs[128][72];
    int bm = blockIdx.y, bn = blockIdx.x;
    int tid = threadIdx.x, lane = tid & 31, warp = tid >> 5;
    int arow = tid >> 3, acg = tid & 7;
    const uint4* a0p = (const uint4*)(g_h + (bm * 64 + arow) * NH + acg * 8);
    const uint4* a1p = (const uint4*)(g_h + (bm * 64 + arow + 32) * NH + acg * 8);
    const uint4* bp[4]; bool bv[4];
#pragma unroll
    for (int i = 0; i < 4; i++) {
        int ng = bn * 128 + arow + i * 32;
        bv[i] = ng < NV;
        bp[i] = (const uint4*)(g_logW + (size_t)(bv[i] ? ng : 0) * NH + acg * 8);
    }
    uint4 z4 = make_uint4(0, 0, 0, 0);
    uint4 ra0 = a0p[0], ra1 = a1p[0], rb[4];
#pragma unroll
    for (int i = 0; i < 4; i++) rb[i] = bv[i] ? bp[i][0] : z4;
    int wm = warp >> 2, wn = warp & 3;
    uint32_t ab0 = smem_u32(&As[wm * 32 + (lane & 15)][(lane >> 4) * 8]);
    uint32_t ab1 = ab0 + 16 * 72 * 2;
    uint32_t bb0 = smem_u32(&Bs[wn * 32 + (lane & 15)][(lane >> 4) * 8]);
    uint32_t bb1 = bb0 + 16 * 72 * 2;
    float acc[2][2][2][4] = {};
#pragma unroll 1
    for (int kk = 0; kk < 8; kk++) {
        *(uint4*)&As[arow][acg * 8] = ra0;
        *(uint4*)&As[arow + 32][acg * 8] = ra1;
#pragma unroll
        for (int i = 0; i < 4; i++) *(uint4*)&Bs[arow + i * 32][acg * 8] = rb[i];
        __syncthreads();
        if (kk < 7) {
            ra0 = a0p[(kk + 1) * 8]; ra1 = a1p[(kk + 1) * 8];
#pragma unroll
            for (int i = 0; i < 4; i++) rb[i] = bv[i] ? bp[i][(kk + 1) * 8] : z4;
        }
#pragma unroll
        for (int k16 = 0; k16 < 4; k16++) {
            uint32_t a0[4], a1[4], q0[4], q1[4];
            ldm_x4(a0, ab0 + k16 * 32); ldm_x4(a1, ab1 + k16 * 32);
            ldm_x4(q0, bb0 + k16 * 32); ldm_x4(q1, bb1 + k16 * 32);
            uint32_t b00[2] = {q0[0], q0[2]}, b01[2] = {q0[1], q0[3]};
            uint32_t b10[2] = {q1[0], q1[2]}, b11[2] = {q1[1], q1[3]};
            mma16816(acc[0][0][0], a0, b00); mma16816(acc[0][0][1], a0, b01);
            mma16816(acc[1][0][0], a1, b00); mma16816(acc[1][0][1], a1, b01);
            mma16816(acc[0][1][0], a0, b10); mma16816(acc[0][1][1], a0, b11);
            mma16816(acc[1][1][0], a1, b10); mma16816(acc[1][1][1], a1, b11);
        }
        __syncthreads();
    }
    int g = lane >> 2, tg = lane & 3;
#pragma unroll
    for (int mt = 0; mt < 2; mt++) {
        int row = bm * 64 + wm * 32 + mt * 16 + g;
#pragma unroll
        for (int nt = 0; nt < 2; nt++)
#pragma unroll
            for (int s = 0; s < 2; s++) {
                int col = bn * 128 + wn * 32 + nt * 16 + s * 8 + tg * 2;
                if (col < NV) {
                    float2 bb = *(const float2*)(lb + col);
                    float* q = acc[mt][nt][s];
                    *(float2*)&out[row * NV + col]       = make_float2(q[0] + bb.x, q[1] + bb.y);
                    *(float2*)&out[(row + 8) * NV + col] = make_float2(q[2] + bb.x, q[3] + bb.y);
                }
            }
    }
}

// ---------- in-place log_softmax, one block per row, row cached in smem ----------
__global__ __launch_bounds__(256) void logsoftmax_kernel(float* __restrict__ out) {
    __shared__ __align__(16) float buf[NV];
    __shared__ float red[10];
    float* p = out + (size_t)blockIdx.x * NV;
    int tid = threadIdx.x, lane = tid & 31, wid = tid >> 5;
    const float4* p4 = (const float4*)p;
    float4* b4 = (float4*)buf;
    float mx = -1e30f;
    for (int i = tid; i < NV / 4; i += 256) {
        float4 v = p4[i]; b4[i] = v;
        mx = fmaxf(fmaxf(mx, v.x), fmaxf(v.y, fmaxf(v.z, v.w)));
    }
#pragma unroll
    for (int o = 16; o; o >>= 1) mx = fmaxf(mx, __shfl_xor_sync(~0u, mx, o));
    if (!lane) red[wid] = mx;
    __syncthreads();
    if (tid == 0) {
        float m = red[0];
        for (int w = 1; w < 8; w++) m = fmaxf(m, red[w]);
        red[8] = m;
    }
    __syncthreads();
    mx = red[8];
    float s = 0.f;
    for (int i = tid; i < NV / 4; i += 256) {
        float4 v = b4[i];
        s += __expf(v.x - mx) + __expf(v.y - mx) + __expf(v.z - mx) + __expf(v.w - mx);
    }
#pragma unroll
    for (int o = 16; o; o >>= 1) s += __shfl_xor_sync(~0u, s, o);
    if (!lane) red[wid] = s;
    __syncthreads();
    if (tid == 0) {
        float t = 0.f;
        for (int w = 0; w < 8; w++) t += red[w];
        red[9] = mx + logf(t);
    }
    __syncthreads();
    float lse = red[9];
    for (int i = tid; i < NV / 4; i += 256) {
        float4 v = b4[i];
        ((float4*)p)[i] = make_float4(v.x - lse, v.y - lse, v.z - lse, v.w - lse);
    }
}

extern "C" void kernel_launch(void* const* d_in, const int* in_sizes, int n_in,
                              void* d_out, int out_size) {
    const int*   wi    = (const int*)d_in[0];
    const int*   fi    = (const int*)d_in[1];
    const float* feats = (const float*)d_in[2];
    const float* embed = (const float*)d_in[3];
    const float* fcW   = (const float*)d_in[4];
    const float* fcb   = (const float*)d_in[5];
    const float* Wf1   = (const float*)d_in[6];
    const float* bf1   = (const float*)d_in[7];
    const float* Wf2   = (const float*)d_in[8];
    const float* bf2   = (const float*)d_in[9];
    const float* WH    = (const float*)d_in[10];
    const float* bH    = (const float*)d_in[11];
    const float* WI    = (const float*)d_in[12];
    const float* bI    = (const float*)d_in[13];
    const float* logW  = (const float*)d_in[14];
    const float* logb  = (const float*)d_in[15];
    float* out = (float*)d_out;

    init_convert<<<4096, 256>>>(embed, WH, WI, Wf1, Wf2, logW);
    att_kernel<<<2048, 256>>>(feats, fcW, fcb);
    for (int t = 0; t < NT; t++) {
        step_gemm<<<160, 256>>>();
        step_combine<<<64, 256>>>(t, wi, fi, bH, bI, bf1, bf2);
    }
    logits_gemm<<<dim3(79, 48), 256>>>(logb, out);
    logsoftmax_kernel<<<NB * NT, 256>>>(out);
}